// round 9
// baseline (speedup 1.0000x reference)
#include <cuda_runtime.h>
#include <cuda_bf16.h>
#include <math.h>
#include <stdint.h>

// Problem constants (match reference setup_inputs)
#define NN    50000
#define EEDG  500000
#define CIN   128
#define HIDC  64
#define NHEAD 4
#define C2    256   // NHEAD * HIDC

// =================== scratch (static __device__) ===================
__device__ float g_XL [NN * C2];
__device__ float g_XR [NN * C2];
__device__ float g_LG [EEDG * NHEAD];    // per-edge per-head logits (8 MB)
__device__ float g_H0 [NN * HIDC];
__device__ float g_H1 [NN * HIDC];
__device__ float g_RES[NN * HIDC];
__device__ int   g_off[NN + 1];
__device__ int   g_cur[NN];
__device__ int   g_eid[EEDG];
__device__ int   g_cnt[NN];
__device__ int   g_bsum[64];
__device__ __align__(16) char g_Bimg[950272];   // bf16 hi/lo weight images (plain row-major)

// =================== PTX helpers (compute_103-legal only) ===================
__device__ __forceinline__ uint32_t smem_to_u32(const void* p) {
    uint32_t a;
    asm("{ .reg .u64 t; cvta.to.shared.u64 t, %1; cvt.u32.u64 %0, t; }" : "=r"(a) : "l"(p));
    return a;
}
__device__ __forceinline__ void ldsm4(uint32_t* r, uint32_t a) {
    asm volatile("ldmatrix.sync.aligned.m8n8.x4.shared.b16 {%0,%1,%2,%3}, [%4];"
        : "=r"(r[0]), "=r"(r[1]), "=r"(r[2]), "=r"(r[3]) : "r"(a));
}
__device__ __forceinline__ void ldsm4t(uint32_t* r, uint32_t a) {
    asm volatile("ldmatrix.sync.aligned.m8n8.x4.trans.shared.b16 {%0,%1,%2,%3}, [%4];"
        : "=r"(r[0]), "=r"(r[1]), "=r"(r[2]), "=r"(r[3]) : "r"(a));
}
__device__ __forceinline__ void mma16816(float* c, const uint32_t* a, const uint32_t* b) {
    asm volatile(
        "mma.sync.aligned.m16n8k16.row.col.f32.bf16.bf16.f32 "
        "{%0,%1,%2,%3}, {%4,%5,%6,%7}, {%8,%9}, {%0,%1,%2,%3};"
        : "+f"(c[0]), "+f"(c[1]), "+f"(c[2]), "+f"(c[3])
        : "r"(a[0]), "r"(a[1]), "r"(a[2]), "r"(a[3]), "r"(b[0]), "r"(b[1]));
}

// =================== CSR build ===================
__global__ void hist_kernel(const int* __restrict__ dst, int E, int* __restrict__ cnt) {
    int e = blockIdx.x * blockDim.x + threadIdx.x;
    if (e < E) atomicAdd(&cnt[dst[e]], 1);
}
__global__ void scan_block(const int* __restrict__ cnt, int N,
                           int* __restrict__ off, int* __restrict__ bsum) {
    __shared__ int s[1024];
    int i = blockIdx.x * 1024 + threadIdx.x;
    int v = (i < N) ? cnt[i] : 0;
    s[threadIdx.x] = v;
    __syncthreads();
    #pragma unroll
    for (int d = 1; d < 1024; d <<= 1) {
        int t = (threadIdx.x >= d) ? s[threadIdx.x - d] : 0;
        __syncthreads();
        if (threadIdx.x >= d) s[threadIdx.x] += t;
        __syncthreads();
    }
    if (i < N) off[i] = s[threadIdx.x] - v;
    if (threadIdx.x == 1023) bsum[blockIdx.x] = s[1023];
}
__global__ void scan_small(int* bsum, int nb) {
    if (threadIdx.x == 0 && blockIdx.x == 0) {
        int acc = 0;
        for (int i = 0; i < nb; i++) { int v = bsum[i]; bsum[i] = acc; acc += v; }
    }
}
__global__ void finalize_offsets(int N, int E, const int* __restrict__ bsum,
                                 int* __restrict__ off, int* __restrict__ cur) {
    int i = blockIdx.x * blockDim.x + threadIdx.x;
    if (i < N) { int v = off[i] + bsum[i >> 10]; off[i] = v; cur[i] = v; }
    if (i == 0) off[N] = E;
}
__global__ void scatter_kernel(const int* __restrict__ dst, int E,
                               int* __restrict__ cur, int* __restrict__ eid) {
    int e = blockIdx.x * blockDim.x + threadIdx.x;
    if (e < E) { int p = atomicAdd(&cur[dst[e]], 1); eid[p] = e; }
}

// =================== weight prep: W[K,N] fp32 -> bf16 hi (img[0:K*N]) + lo (img[K*N:]) ===================
__global__ void prep_B(const float* __restrict__ W, int K, int N, __nv_bfloat16* __restrict__ img) {
    int i = blockIdx.x * blockDim.x + threadIdx.x;
    if (i >= K * N) return;
    float a = W[i];
    __nv_bfloat16 h = __float2bfloat16(a);
    __nv_bfloat16 l = __float2bfloat16(a - __bfloat162float(h));
    img[i] = h;
    img[K * N + i] = l;
}

// =================== shared GEMM core (A/B smem fill + hi/lo 3-pass mainloop) ===================
// CTA = 128 rows x 128 cols (grid.y = 128-col chunk). 256 threads = 8 warps (2M x 4N),
// warp tile 64x32 = 4x4 m16n8k16. acc[mi][ni] = {r.c0, r.c1, (r+8).c0, (r+8).c1}.
struct GemmAcc { float a[4][4][4]; };

__device__ __forceinline__ void gemm_core(
    int M, int K, const float* __restrict__ A, const __nv_bfloat16* __restrict__ Bimg,
    int Nfull, int m0, int n0, char* smem, GemmAcc& R)
{
    const int tid = threadIdx.x, wid = tid >> 5, lane = tid & 31;
    const int PA = K + 8, PB = 136;
    const uint32_t A_sz = (uint32_t)128 * PA * 2;
    const uint32_t B_sz = (uint32_t)K * PB * 2;
    char* Ah = smem;
    char* Al = smem + A_sz;
    char* Bh = smem + 2 * A_sz;
    char* Bl = smem + 2 * A_sz + B_sz;

    // A tile: fp32 -> bf16 hi/lo
    {
        const int rf4 = K >> 2;
        for (int idx = tid; idx < 128 * rf4; idx += 256) {
            int row = idx / rf4, col = (idx - row * rf4) * 4;
            int gr = m0 + row;
            float4 v = make_float4(0.f, 0.f, 0.f, 0.f);
            if (gr < M) v = *(const float4*)(A + (size_t)gr * K + col);
            float f[4] = {v.x, v.y, v.z, v.w};
            uint32_t hp[2], lp[2];
            #pragma unroll
            for (int q = 0; q < 2; q++) {
                float a0 = f[2 * q], a1 = f[2 * q + 1];
                __nv_bfloat16 h0 = __float2bfloat16(a0), h1 = __float2bfloat16(a1);
                __nv_bfloat16 l0 = __float2bfloat16(a0 - __bfloat162float(h0));
                __nv_bfloat16 l1 = __float2bfloat16(a1 - __bfloat162float(h1));
                hp[q] = ((uint32_t)__bfloat16_as_ushort(h1) << 16) | __bfloat16_as_ushort(h0);
                lp[q] = ((uint32_t)__bfloat16_as_ushort(l1) << 16) | __bfloat16_as_ushort(l0);
            }
            uint32_t boff = ((uint32_t)row * PA + col) * 2;
            *(uint32_t*)(Ah + boff)     = hp[0];
            *(uint32_t*)(Ah + boff + 4) = hp[1];
            *(uint32_t*)(Al + boff)     = lp[0];
            *(uint32_t*)(Al + boff + 4) = lp[1];
        }
    }
    // B tile: copy hi/lo images
    {
        const __nv_bfloat16* gh = Bimg;
        const __nv_bfloat16* gl = Bimg + (size_t)K * Nfull;
        for (int idx = tid; idx < K * 16; idx += 256) {
            int row = idx >> 4, col = (idx & 15) * 8;
            uint4 vh = make_uint4(0, 0, 0, 0), vl = vh;
            if (n0 + col < Nfull) {
                vh = *(const uint4*)(gh + (size_t)row * Nfull + n0 + col);
                vl = *(const uint4*)(gl + (size_t)row * Nfull + n0 + col);
            }
            uint32_t boff = ((uint32_t)row * PB + col) * 2;
            *(uint4*)(Bh + boff) = vh;
            *(uint4*)(Bl + boff) = vl;
        }
    }
    __syncthreads();

    const int wm = (wid >> 2) * 64;
    const int wn = (wid & 3) * 32;
    const int lr = lane & 15, lc = lane >> 4;

    #pragma unroll
    for (int i = 0; i < 4; i++)
        #pragma unroll
        for (int j = 0; j < 4; j++)
            #pragma unroll
            for (int q = 0; q < 4; q++) R.a[i][j][q] = 0.f;

    const uint32_t su = smem_to_u32(smem);
    const uint32_t aAddr0 = su + (((uint32_t)(wm + lr) * PA + lc * 8) * 2);
    const uint32_t bAddr0 = su + 2 * A_sz + (((uint32_t)lr * PB + wn + lc * 8) * 2);
    const int ksteps = K >> 4;

    for (int ks = 0; ks < ksteps; ks++) {
        const uint32_t ka = aAddr0 + (uint32_t)ks * 32;
        const uint32_t kb = bAddr0 + (uint32_t)ks * 16 * PB * 2;
        uint32_t a[4][4], bh[4][2], bl[4][2];
        #pragma unroll
        for (int mi = 0; mi < 4; mi++) ldsm4(a[mi], ka + (uint32_t)mi * 16 * PA * 2);
        #pragma unroll
        for (int nj = 0; nj < 2; nj++) {
            uint32_t t[4];
            ldsm4t(t, kb + (uint32_t)nj * 32);
            bh[2 * nj][0] = t[0]; bh[2 * nj][1] = t[1];
            bh[2 * nj + 1][0] = t[2]; bh[2 * nj + 1][1] = t[3];
            ldsm4t(t, kb + B_sz + (uint32_t)nj * 32);
            bl[2 * nj][0] = t[0]; bl[2 * nj][1] = t[1];
            bl[2 * nj + 1][0] = t[2]; bl[2 * nj + 1][1] = t[3];
        }
        #pragma unroll
        for (int mi = 0; mi < 4; mi++)
            #pragma unroll
            for (int ni = 0; ni < 4; ni++) mma16816(R.a[mi][ni], a[mi], bh[ni]);
        #pragma unroll
        for (int mi = 0; mi < 4; mi++)
            #pragma unroll
            for (int ni = 0; ni < 4; ni++) mma16816(R.a[mi][ni], a[mi], bl[ni]);
        #pragma unroll
        for (int mi = 0; mi < 4; mi++) ldsm4(a[mi], ka + A_sz + (uint32_t)mi * 16 * PA * 2);
        #pragma unroll
        for (int mi = 0; mi < 4; mi++)
            #pragma unroll
            for (int ni = 0; ni < 4; ni++) mma16816(R.a[mi][ni], a[mi], bh[ni]);
    }
}

// ---- plain GEMM (node transforms): store C + bias ----
__global__ __launch_bounds__(256) void tc_gemm(
    int M, int K, int N,
    const float* __restrict__ A, const __nv_bfloat16* __restrict__ Bimg,
    const float* __restrict__ bias, float* __restrict__ C)
{
    extern __shared__ char smem[];
    const int lane = threadIdx.x & 31, wid = threadIdx.x >> 5;
    const int m0 = blockIdx.x * 128, n0 = blockIdx.y * 128;
    GemmAcc R;
    gemm_core(M, K, A, Bimg, N, m0, n0, smem, R);

    const int wm = (wid >> 2) * 64, wn = (wid & 3) * 32;
    #pragma unroll
    for (int mi = 0; mi < 4; mi++) {
        int row = m0 + wm + mi * 16 + (lane >> 2);
        #pragma unroll
        for (int ni = 0; ni < 4; ni++) {
            int col = n0 + wn + ni * 8 + (lane & 3) * 2;
            if (col < N) {
                float b0 = bias ? bias[col]     : 0.f;
                float b1 = bias ? bias[col + 1] : 0.f;
                if (row < M) {
                    float2 v = make_float2(R.a[mi][ni][0] + b0, R.a[mi][ni][1] + b1);
                    *(float2*)(C + (size_t)row * N + col) = v;
                }
                if (row + 8 < M) {
                    float2 v = make_float2(R.a[mi][ni][2] + b0, R.a[mi][ni][3] + b1);
                    *(float2*)(C + (size_t)(row + 8) * N + col) = v;
                }
            }
        }
    }
}

// ---- fused edge GEMM: ee stays in registers; epilogue computes partial logits ----
// logit[e,h] += sum_{c in chunk} att[c] * leakyrelu(ee + XL[src[e],c] + XR[dst[e],c])
__global__ __launch_bounds__(256) void tc_gemm_edge(
    int E, int K,
    const float* __restrict__ A, const __nv_bfloat16* __restrict__ Bimg,
    const float* __restrict__ XLg, const float* __restrict__ XRg,
    const int* __restrict__ src, const int* __restrict__ dst,
    const float* __restrict__ attv, float* __restrict__ logits)
{
    extern __shared__ char smem[];
    const int lane = threadIdx.x & 31, wid = threadIdx.x >> 5;
    const int m0 = blockIdx.x * 128, n0 = blockIdx.y * 128;
    GemmAcc R;
    gemm_core(E, K, A, Bimg, C2, m0, n0, smem, R);

    const int wm = (wid >> 2) * 64, wn = (wid & 3) * 32;
    const int colq = n0 + wn + (lane & 3) * 2;       // this thread's first col
    const int head = (n0 + wn) >> 6;                  // whole warp tile in one head

    // att values for this thread's 8 columns (2 per ni)
    float av[4][2];
    #pragma unroll
    for (int ni = 0; ni < 4; ni++) {
        float2 t = *(const float2*)(attv + colq + ni * 8);
        av[ni][0] = t.x; av[ni][1] = t.y;
    }

    #pragma unroll
    for (int mi = 0; mi < 4; mi++) {
        #pragma unroll
        for (int half = 0; half < 2; half++) {
            int row = m0 + wm + mi * 16 + (lane >> 2) + half * 8;
            float part = 0.f;
            if (row < E) {
                const float* xlr = XLg + (size_t)src[row] * C2;
                const float* xrr = XRg + (size_t)dst[row] * C2;
                #pragma unroll
                for (int ni = 0; ni < 4; ni++) {
                    int c = colq + ni * 8;
                    float2 xl2 = *(const float2*)(xlr + c);
                    float2 xr2 = *(const float2*)(xrr + c);
                    float z0 = R.a[mi][ni][half * 2 + 0] + xl2.x + xr2.x;
                    float z1 = R.a[mi][ni][half * 2 + 1] + xl2.y + xr2.y;
                    z0 = (z0 > 0.f) ? z0 : 0.2f * z0;
                    z1 = (z1 > 0.f) ? z1 : 0.2f * z1;
                    part = fmaf(av[ni][0], z0, part);
                    part = fmaf(av[ni][1], z1, part);
                }
            }
            // quad reduction over the 4 lanes covering this row's 32 cols
            part += __shfl_xor_sync(0xffffffffu, part, 1);
            part += __shfl_xor_sync(0xffffffffu, part, 2);
            if ((lane & 3) == 0 && row < E)
                atomicAdd(&logits[row * NHEAD + head], part);
        }
    }
}

// =================== lean aggregation: precomputed logits, one warp per node ===================
__global__ void gat_aggregate(int n_nodes,
                              const float* __restrict__ XL,
                              const float* __restrict__ LG,
                              const int* __restrict__ off, const int* __restrict__ eid,
                              const int* __restrict__ src,
                              const float* __restrict__ bias,
                              const float* __restrict__ bng, const float* __restrict__ bnb,
                              const float* __restrict__ bnrm, const float* __restrict__ bnrv,
                              const float* __restrict__ residual,
                              float* __restrict__ outp, int bnrelu) {
    int gw   = (blockIdx.x * blockDim.x + threadIdx.x) >> 5;
    int lane = threadIdx.x & 31;
    if (gw >= n_nodes) return;
    const int n = gw;
    const int base = lane * 8;
    const int head = lane >> 3;

    float m = -1e30f, dsum = 0.f;
    float acc[8];
    #pragma unroll
    for (int j = 0; j < 8; j++) acc[j] = 0.f;

    const int i0 = off[n], i1 = off[n + 1];
    for (int idx = i0; idx < i1; ++idx) {
        int e = eid[idx];
        int s = src[e];
        float p = __ldg(&LG[e * NHEAD + head]);
        float el[8];
        {
            float4 t0 = *(const float4*)(XL + (size_t)s * C2 + base);
            float4 t1 = *(const float4*)(XL + (size_t)s * C2 + base + 4);
            el[0]=t0.x; el[1]=t0.y; el[2]=t0.z; el[3]=t0.w;
            el[4]=t1.x; el[5]=t1.y; el[6]=t1.z; el[7]=t1.w;
        }
        float nm = fmaxf(m, p);
        float sc = __expf(m - nm);
        float f  = __expf(p - nm);
        dsum = dsum * sc + f;
        #pragma unroll
        for (int j = 0; j < 8; j++) acc[j] = fmaf(acc[j], sc, f * el[j]);
        m = nm;
    }

    float inv = (i1 > i0) ? (1.0f / dsum) : 0.f;
    float v[8];
    #pragma unroll
    for (int j = 0; j < 8; j++) {
        float t = acc[j] * inv;
        t += __shfl_xor_sync(0xffffffffu, t, 8);
        t += __shfl_xor_sync(0xffffffffu, t, 16);
        v[j] = t * 0.25f;
    }

    if (lane < 8) {
        int c0 = lane * 8;
        #pragma unroll
        for (int j = 0; j < 8; j++) {
            int c = c0 + j;
            float t = v[j] + bias[c];
            if (bnrelu) {
                t = (t - bnrm[c]) * rsqrtf(bnrv[c] + 1e-5f) * bng[c] + bnb[c];
                t += residual[(size_t)n * HIDC + c];
                t = fmaxf(t, 0.f);
            }
            outp[(size_t)n * HIDC + c] = t;
        }
    }
}

__global__ void copy_f4(const float4* __restrict__ s, float4* __restrict__ d, int n4) {
    int i = blockIdx.x * blockDim.x + threadIdx.x;
    int stride = gridDim.x * blockDim.x;
    for (; i < n4; i += stride) d[i] = s[i];
}

static inline int cdiv(int a, int b) { return (a + b - 1) / b; }
static inline size_t img_bytes(int K, int N) { return (size_t)4 * K * N; }
static inline int smem_size(int K) {
    return 2 * (128 * (K + 8) * 2) + 2 * (K * 136 * 2);
}

extern "C" void kernel_launch(void* const* d_in, const int* in_sizes, int n_in,
                              void* d_out, int out_size) {
    const float* x      = (const float*)d_in[0];
    const int*   ei     = (const int*)  d_in[1];
    const float* ea     = (const float*)d_in[2];
    const float* res_W  = (const float*)d_in[3];
    const float* res_b  = (const float*)d_in[4];
    const float* Wl0    = (const float*)d_in[5];
    const float* bl0    = (const float*)d_in[6];
    const float* Wr0    = (const float*)d_in[7];
    const float* br0    = (const float*)d_in[8];
    const float* We0    = (const float*)d_in[9];
    const float* att0   = (const float*)d_in[10];
    const float* bias0  = (const float*)d_in[11];
    const float* Wl12   = (const float*)d_in[12];
    const float* bl12   = (const float*)d_in[13];
    const float* Wr12   = (const float*)d_in[14];
    const float* br12   = (const float*)d_in[15];
    const float* We12   = (const float*)d_in[16];
    const float* att12  = (const float*)d_in[17];
    const float* bias12 = (const float*)d_in[18];
    const float* bng    = (const float*)d_in[19];
    const float* bnb    = (const float*)d_in[20];
    const float* bnrm   = (const float*)d_in[21];
    const float* bnrv   = (const float*)d_in[22];

    const int N = in_sizes[0] / CIN;
    const int E = in_sizes[1] / 2;
    const int* srcp = ei;
    const int* dstp = ei + E;
    float* out = (float*)d_out;

    float *XL, *XR, *LG, *H0, *H1, *RES;
    int *off, *cur, *eid, *cnt, *bsum;
    char* Bimg;
    cudaGetSymbolAddress((void**)&XL,  g_XL);
    cudaGetSymbolAddress((void**)&XR,  g_XR);
    cudaGetSymbolAddress((void**)&LG,  g_LG);
    cudaGetSymbolAddress((void**)&H0,  g_H0);
    cudaGetSymbolAddress((void**)&H1,  g_H1);
    cudaGetSymbolAddress((void**)&RES, g_RES);
    cudaGetSymbolAddress((void**)&off, g_off);
    cudaGetSymbolAddress((void**)&cur, g_cur);
    cudaGetSymbolAddress((void**)&eid, g_eid);
    cudaGetSymbolAddress((void**)&cnt, g_cnt);
    cudaGetSymbolAddress((void**)&bsum,g_bsum);
    cudaGetSymbolAddress((void**)&Bimg,g_Bimg);

    cudaFuncSetAttribute(tc_gemm,      cudaFuncAttributeMaxDynamicSharedMemorySize, smem_size(128));
    cudaFuncSetAttribute(tc_gemm_edge, cudaFuncAttributeMaxDynamicSharedMemorySize, smem_size(128));

    // ---- weight image offsets (4 bytes per element: hi+lo bf16) ----
    size_t o = 0;
    const size_t OFF_RES = o; o += img_bytes(128, 64);
    const size_t OFF_WL0 = o; o += img_bytes(128, 256);
    const size_t OFF_WR0 = o; o += img_bytes(128, 256);
    const size_t OFF_WE0 = o; o += img_bytes(128, 256);
    const size_t OFF_WL1 = o; o += img_bytes(64, 256);
    const size_t OFF_WR1 = o; o += img_bytes(64, 256);
    const size_t OFF_WE1 = o; o += img_bytes(128, 256);
    const size_t OFF_WL2 = o; o += img_bytes(64, 256);
    const size_t OFF_WR2 = o; o += img_bytes(64, 256);
    const size_t OFF_WE2 = o; o += img_bytes(128, 256);

    #define IMG(off) ((__nv_bfloat16*)(Bimg + (off)))
    prep_B<<<cdiv(128 *  64, 256), 256>>>(res_W,            128,  64, IMG(OFF_RES));
    prep_B<<<cdiv(128 * 256, 256), 256>>>(Wl0,              128, 256, IMG(OFF_WL0));
    prep_B<<<cdiv(128 * 256, 256), 256>>>(Wr0,              128, 256, IMG(OFF_WR0));
    prep_B<<<cdiv(128 * 256, 256), 256>>>(We0,              128, 256, IMG(OFF_WE0));
    prep_B<<<cdiv( 64 * 256, 256), 256>>>(Wl12,              64, 256, IMG(OFF_WL1));
    prep_B<<<cdiv( 64 * 256, 256), 256>>>(Wr12,              64, 256, IMG(OFF_WR1));
    prep_B<<<cdiv(128 * 256, 256), 256>>>(We12,             128, 256, IMG(OFF_WE1));
    prep_B<<<cdiv( 64 * 256, 256), 256>>>(Wl12 + HIDC * C2,  64, 256, IMG(OFF_WL2));
    prep_B<<<cdiv( 64 * 256, 256), 256>>>(Wr12 + HIDC * C2,  64, 256, IMG(OFF_WR2));
    prep_B<<<cdiv(128 * 256, 256), 256>>>(We12 + CIN * C2,  128, 256, IMG(OFF_WE2));

    // ---- CSR by destination ----
    cudaMemsetAsync(cnt, 0, sizeof(int) * N);
    hist_kernel<<<cdiv(E, 256), 256>>>(dstp, E, cnt);
    int nb = cdiv(N, 1024);
    scan_block<<<nb, 1024>>>(cnt, N, off, bsum);
    scan_small<<<1, 32>>>(bsum, nb);
    finalize_offsets<<<cdiv(N, 256), 256>>>(N, E, bsum, off, cur);
    scatter_kernel<<<cdiv(E, 256), 256>>>(dstp, E, cur, eid);

    const int smK128 = smem_size(128);
    const int smK64  = smem_size(64);
    dim3 gN2(cdiv(N, 128), 2);
    dim3 gE2(cdiv(E, 128), 2);
    dim3 gR (cdiv(N, 128), 1);
    int aggGrid = cdiv(N * 32, 256);

    // ---- residual projection ----
    tc_gemm<<<gR, 256, smK128>>>(N, 128, 64, x, IMG(OFF_RES), res_b, RES);

    // ---- layer 0 ----
    tc_gemm<<<gN2, 256, smK128>>>(N, 128, 256, x,  IMG(OFF_WL0), bl0, XL);
    tc_gemm<<<gN2, 256, smK128>>>(N, 128, 256, x,  IMG(OFF_WR0), br0, XR);
    cudaMemsetAsync(LG, 0, (size_t)E * NHEAD * sizeof(float));
    tc_gemm_edge<<<gE2, 256, smK128>>>(E, 128, ea, IMG(OFF_WE0),
                                       XL, XR, srcp, dstp, att0, LG);
    gat_aggregate<<<aggGrid, 256>>>(N, XL, LG, off, eid, srcp,
                                    bias0, bng, bnb, bnrm, bnrv, RES, H0, 1);

    // ---- layer 1 ----
    tc_gemm<<<gN2, 256, smK64>>>(N, 64, 256, H0, IMG(OFF_WL1), bl12, XL);
    tc_gemm<<<gN2, 256, smK64>>>(N, 64, 256, H0, IMG(OFF_WR1), br12, XR);
    cudaMemsetAsync(LG, 0, (size_t)E * NHEAD * sizeof(float));
    tc_gemm_edge<<<gE2, 256, smK128>>>(E, 128, ea, IMG(OFF_WE1),
                                       XL, XR, srcp, dstp, att12, LG);
    gat_aggregate<<<aggGrid, 256>>>(N, XL, LG, off, eid, srcp,
                                    bias12, bng + HIDC, bnb + HIDC,
                                    bnrm + HIDC, bnrv + HIDC, H0, H1, 1);

    // ---- layer 2 (final conv) ----
    tc_gemm<<<gN2, 256, smK64>>>(N, 64, 256, H1, IMG(OFF_WL2), bl12 + C2, XL);
    tc_gemm<<<gN2, 256, smK64>>>(N, 64, 256, H1, IMG(OFF_WR2), br12 + C2, XR);
    cudaMemsetAsync(LG, 0, (size_t)E * NHEAD * sizeof(float));
    tc_gemm_edge<<<gE2, 256, smK128>>>(E, 128, ea, IMG(OFF_WE2),
                                       XL, XR, srcp, dstp, att12 + C2, LG);
    gat_aggregate<<<aggGrid, 256>>>(N, XL, LG, off, eid, srcp,
                                    bias12 + HIDC,
                                    nullptr, nullptr, nullptr, nullptr, nullptr, out, 0);

    // ---- second output: edge_attr passthrough ----
    copy_f4<<<4096, 256>>>((const float4*)ea, (float4*)(out + (size_t)N * HIDC),
                           E * CIN / 4);
    #undef IMG
}

// round 10
// speedup vs baseline: 1.5445x; 1.5445x over previous
#include <cuda_runtime.h>
#include <cuda_bf16.h>
#include <math.h>
#include <stdint.h>

// Problem constants (match reference setup_inputs)
#define NN    50000
#define EEDG  500000
#define CIN   128
#define HIDC  64
#define NHEAD 4
#define C2    256   // NHEAD * HIDC

// =================== scratch (static __device__) ===================
__device__ float g_XL [NN * C2];
__device__ float g_XR [NN * C2];
__device__ __nv_bfloat16 g_EE [(size_t)EEDG * C2];   // 256 MB, CSR-permuted rows
__device__ float g_H0 [NN * HIDC];
__device__ float g_H1 [NN * HIDC];
__device__ float g_RES[NN * HIDC];
__device__ int   g_off[NN + 1];
__device__ int   g_cur[NN];
__device__ int   g_pos[EEDG];      // CSR slot of edge e
__device__ int   g_srcp[EEDG];     // src node, permuted to CSR order
__device__ int   g_cnt[NN];
__device__ int   g_bsum[64];
__device__ __align__(16) char g_Bimg[950272];   // bf16 hi/lo weight images (plain row-major)

// =================== PTX helpers (compute_103-legal only) ===================
__device__ __forceinline__ uint32_t smem_to_u32(const void* p) {
    uint32_t a;
    asm("{ .reg .u64 t; cvta.to.shared.u64 t, %1; cvt.u32.u64 %0, t; }" : "=r"(a) : "l"(p));
    return a;
}
__device__ __forceinline__ void ldsm4(uint32_t* r, uint32_t a) {
    asm volatile("ldmatrix.sync.aligned.m8n8.x4.shared.b16 {%0,%1,%2,%3}, [%4];"
        : "=r"(r[0]), "=r"(r[1]), "=r"(r[2]), "=r"(r[3]) : "r"(a));
}
__device__ __forceinline__ void ldsm4t(uint32_t* r, uint32_t a) {
    asm volatile("ldmatrix.sync.aligned.m8n8.x4.trans.shared.b16 {%0,%1,%2,%3}, [%4];"
        : "=r"(r[0]), "=r"(r[1]), "=r"(r[2]), "=r"(r[3]) : "r"(a));
}
__device__ __forceinline__ void mma16816(float* c, const uint32_t* a, const uint32_t* b) {
    asm volatile(
        "mma.sync.aligned.m16n8k16.row.col.f32.bf16.bf16.f32 "
        "{%0,%1,%2,%3}, {%4,%5,%6,%7}, {%8,%9}, {%0,%1,%2,%3};"
        : "+f"(c[0]), "+f"(c[1]), "+f"(c[2]), "+f"(c[3])
        : "r"(a[0]), "r"(a[1]), "r"(a[2]), "r"(a[3]), "r"(b[0]), "r"(b[1]));
}

// =================== CSR build ===================
__global__ void hist_kernel(const int* __restrict__ dst, int E, int* __restrict__ cnt) {
    int e = blockIdx.x * blockDim.x + threadIdx.x;
    if (e < E) atomicAdd(&cnt[dst[e]], 1);
}
__global__ void scan_block(const int* __restrict__ cnt, int N,
                           int* __restrict__ off, int* __restrict__ bsum) {
    __shared__ int s[1024];
    int i = blockIdx.x * 1024 + threadIdx.x;
    int v = (i < N) ? cnt[i] : 0;
    s[threadIdx.x] = v;
    __syncthreads();
    #pragma unroll
    for (int d = 1; d < 1024; d <<= 1) {
        int t = (threadIdx.x >= d) ? s[threadIdx.x - d] : 0;
        __syncthreads();
        if (threadIdx.x >= d) s[threadIdx.x] += t;
        __syncthreads();
    }
    if (i < N) off[i] = s[threadIdx.x] - v;
    if (threadIdx.x == 1023) bsum[blockIdx.x] = s[1023];
}
__global__ void scan_small(int* bsum, int nb) {
    if (threadIdx.x == 0 && blockIdx.x == 0) {
        int acc = 0;
        for (int i = 0; i < nb; i++) { int v = bsum[i]; bsum[i] = acc; acc += v; }
    }
}
__global__ void finalize_offsets(int N, int E, const int* __restrict__ bsum,
                                 int* __restrict__ off, int* __restrict__ cur) {
    int i = blockIdx.x * blockDim.x + threadIdx.x;
    if (i < N) { int v = off[i] + bsum[i >> 10]; off[i] = v; cur[i] = v; }
    if (i == 0) off[N] = E;
}
__global__ void scatter_kernel(const int* __restrict__ dst, const int* __restrict__ src,
                               int E, int* __restrict__ cur,
                               int* __restrict__ pos, int* __restrict__ srcp) {
    int e = blockIdx.x * blockDim.x + threadIdx.x;
    if (e < E) {
        int p = atomicAdd(&cur[dst[e]], 1);
        pos[e] = p;
        srcp[p] = src[e];
    }
}

// =================== weight prep: W[K,N] fp32 -> bf16 hi (img[0:K*N]) + lo (img[K*N:]) ===================
__global__ void prep_B(const float* __restrict__ W, int K, int N, __nv_bfloat16* __restrict__ img) {
    int i = blockIdx.x * blockDim.x + threadIdx.x;
    if (i >= K * N) return;
    float a = W[i];
    __nv_bfloat16 h = __float2bfloat16(a);
    __nv_bfloat16 l = __float2bfloat16(a - __bfloat162float(h));
    img[i] = h;
    img[K * N + i] = l;
}

// =================== shared GEMM core, templated on warp n-subtiles ===================
// CTA = 128 rows x (NT*32) cols. 256 threads = 8 warps (2M x 4N); warp tile 64 x NT*8.
// R[mi][ni] = {r.c0, r.c1, (r+8).c0, (r+8).c1}.
template<int NT>
__device__ __forceinline__ void gemm_core(
    int M, int K, const float* __restrict__ A, const __nv_bfloat16* __restrict__ Bimg,
    int Nfull, int m0, int n0, char* smem, float R[4][NT][4])
{
    const int BN = NT * 32;
    const int tid = threadIdx.x, wid = tid >> 5, lane = tid & 31;
    const int PA = K + 8, PB = BN + 8;
    const uint32_t A_sz = (uint32_t)128 * PA * 2;
    const uint32_t B_sz = (uint32_t)K * PB * 2;
    char* Ah = smem;
    char* Al = smem + A_sz;
    char* Bh = smem + 2 * A_sz;
    char* Bl = smem + 2 * A_sz + B_sz;

    // A tile: fp32 -> bf16 hi/lo
    {
        const int rf4 = K >> 2;
        for (int idx = tid; idx < 128 * rf4; idx += 256) {
            int row = idx / rf4, col = (idx - row * rf4) * 4;
            int gr = m0 + row;
            float4 v = make_float4(0.f, 0.f, 0.f, 0.f);
            if (gr < M) v = *(const float4*)(A + (size_t)gr * K + col);
            float f[4] = {v.x, v.y, v.z, v.w};
            uint32_t hp[2], lp[2];
            #pragma unroll
            for (int q = 0; q < 2; q++) {
                float a0 = f[2 * q], a1 = f[2 * q + 1];
                __nv_bfloat16 h0 = __float2bfloat16(a0), h1 = __float2bfloat16(a1);
                __nv_bfloat16 l0 = __float2bfloat16(a0 - __bfloat162float(h0));
                __nv_bfloat16 l1 = __float2bfloat16(a1 - __bfloat162float(h1));
                hp[q] = ((uint32_t)__bfloat16_as_ushort(h1) << 16) | __bfloat16_as_ushort(h0);
                lp[q] = ((uint32_t)__bfloat16_as_ushort(l1) << 16) | __bfloat16_as_ushort(l0);
            }
            uint32_t boff = ((uint32_t)row * PA + col) * 2;
            *(uint32_t*)(Ah + boff)     = hp[0];
            *(uint32_t*)(Ah + boff + 4) = hp[1];
            *(uint32_t*)(Al + boff)     = lp[0];
            *(uint32_t*)(Al + boff + 4) = lp[1];
        }
    }
    // B tile: copy hi/lo images
    {
        const __nv_bfloat16* gh = Bimg;
        const __nv_bfloat16* gl = Bimg + (size_t)K * Nfull;
        const int c8 = BN / 8;
        for (int idx = tid; idx < K * c8; idx += 256) {
            int row = idx / c8, col = (idx - row * c8) * 8;
            uint4 vh = make_uint4(0, 0, 0, 0), vl = vh;
            if (n0 + col < Nfull) {
                vh = *(const uint4*)(gh + (size_t)row * Nfull + n0 + col);
                vl = *(const uint4*)(gl + (size_t)row * Nfull + n0 + col);
            }
            uint32_t boff = ((uint32_t)row * PB + col) * 2;
            *(uint4*)(Bh + boff) = vh;
            *(uint4*)(Bl + boff) = vl;
        }
    }
    __syncthreads();

    const int wm = (wid >> 2) * 64;
    const int wn = (wid & 3) * (NT * 8);
    const int lr = lane & 15, lc = lane >> 4;

    #pragma unroll
    for (int i = 0; i < 4; i++)
        #pragma unroll
        for (int j = 0; j < NT; j++)
            #pragma unroll
            for (int q = 0; q < 4; q++) R[i][j][q] = 0.f;

    const uint32_t su = smem_to_u32(smem);
    const uint32_t aAddr0 = su + (((uint32_t)(wm + lr) * PA + lc * 8) * 2);
    const uint32_t bAddr0 = su + 2 * A_sz + (((uint32_t)lr * PB + wn + lc * 8) * 2);
    const int ksteps = K >> 4;

    for (int ks = 0; ks < ksteps; ks++) {
        const uint32_t ka = aAddr0 + (uint32_t)ks * 32;
        const uint32_t kb = bAddr0 + (uint32_t)ks * 16 * PB * 2;
        uint32_t a[4][4], bh[NT][2], bl[NT][2];
        #pragma unroll
        for (int mi = 0; mi < 4; mi++) ldsm4(a[mi], ka + (uint32_t)mi * 16 * PA * 2);
        #pragma unroll
        for (int nj = 0; nj < NT / 2; nj++) {
            uint32_t t[4];
            ldsm4t(t, kb + (uint32_t)nj * 32);
            bh[2 * nj][0] = t[0]; bh[2 * nj][1] = t[1];
            bh[2 * nj + 1][0] = t[2]; bh[2 * nj + 1][1] = t[3];
            ldsm4t(t, kb + B_sz + (uint32_t)nj * 32);
            bl[2 * nj][0] = t[0]; bl[2 * nj][1] = t[1];
            bl[2 * nj + 1][0] = t[2]; bl[2 * nj + 1][1] = t[3];
        }
        #pragma unroll
        for (int mi = 0; mi < 4; mi++)
            #pragma unroll
            for (int ni = 0; ni < NT; ni++) mma16816(R[mi][ni], a[mi], bh[ni]);
        #pragma unroll
        for (int mi = 0; mi < 4; mi++)
            #pragma unroll
            for (int ni = 0; ni < NT; ni++) mma16816(R[mi][ni], a[mi], bl[ni]);
        #pragma unroll
        for (int mi = 0; mi < 4; mi++) ldsm4(a[mi], ka + A_sz + (uint32_t)mi * 16 * PA * 2);
        #pragma unroll
        for (int mi = 0; mi < 4; mi++)
            #pragma unroll
            for (int ni = 0; ni < NT; ni++) mma16816(R[mi][ni], a[mi], bh[ni]);
    }
}

// ---- plain GEMM (node transforms): NT=4, store fp32 C + bias ----
__global__ __launch_bounds__(256) void tc_gemm(
    int M, int K, int N,
    const float* __restrict__ A, const __nv_bfloat16* __restrict__ Bimg,
    const float* __restrict__ bias, float* __restrict__ C)
{
    extern __shared__ char smem[];
    const int lane = threadIdx.x & 31, wid = threadIdx.x >> 5;
    const int m0 = blockIdx.x * 128, n0 = blockIdx.y * 128;
    float R[4][4][4];
    gemm_core<4>(M, K, A, Bimg, N, m0, n0, smem, R);

    const int wm = (wid >> 2) * 64, wn = (wid & 3) * 32;
    #pragma unroll
    for (int mi = 0; mi < 4; mi++) {
        int row = m0 + wm + mi * 16 + (lane >> 2);
        #pragma unroll
        for (int ni = 0; ni < 4; ni++) {
            int col = n0 + wn + ni * 8 + (lane & 3) * 2;
            if (col < N) {
                float b0 = bias ? bias[col]     : 0.f;
                float b1 = bias ? bias[col + 1] : 0.f;
                if (row < M) {
                    float2 v = make_float2(R[mi][ni][0] + b0, R[mi][ni][1] + b1);
                    *(float2*)(C + (size_t)row * N + col) = v;
                }
                if (row + 8 < M) {
                    float2 v = make_float2(R[mi][ni][2] + b0, R[mi][ni][3] + b1);
                    *(float2*)(C + (size_t)(row + 8) * N + col) = v;
                }
            }
        }
    }
}

// ---- edge GEMM: NT=8 (full 256 cols in one CTA), store bf16 EE at CSR-permuted rows ----
__global__ __launch_bounds__(256) void tc_gemm_edge(
    int E, int K,
    const float* __restrict__ A, const __nv_bfloat16* __restrict__ Bimg,
    const int* __restrict__ pos, __nv_bfloat16* __restrict__ EE)
{
    extern __shared__ char smem[];
    const int lane = threadIdx.x & 31, wid = threadIdx.x >> 5;
    const int m0 = blockIdx.x * 128;
    float R[4][8][4];
    gemm_core<8>(E, K, A, Bimg, C2, m0, 0, smem, R);

    const int wm = (wid >> 2) * 64, wn = (wid & 3) * 64;
    #pragma unroll
    for (int mi = 0; mi < 4; mi++) {
        #pragma unroll
        for (int half = 0; half < 2; half++) {
            int row = m0 + wm + mi * 16 + (lane >> 2) + half * 8;
            if (row < E) {
                int p = pos[row];
                uint32_t* dstp = (uint32_t*)(EE + (size_t)p * C2 + wn + (lane & 3) * 2);
                #pragma unroll
                for (int ni = 0; ni < 8; ni++) {
                    __nv_bfloat16 h0 = __float2bfloat16(R[mi][ni][half * 2 + 0]);
                    __nv_bfloat16 h1 = __float2bfloat16(R[mi][ni][half * 2 + 1]);
                    uint32_t pk = ((uint32_t)__bfloat16_as_ushort(h1) << 16) | __bfloat16_as_ushort(h0);
                    dstp[ni * 4] = pk;   // ni*8 cols = ni*4 uint32
                }
            }
        }
    }
}

// =================== fused GATv2 aggregation (one warp per destination node) ===================
// EE is bf16, CSR-ordered (sequential). src permuted. Online softmax, mean heads, bias/BN/res.
__global__ void gat_aggregate(int n_nodes,
                              const float* __restrict__ XL, const float* __restrict__ XR,
                              const __nv_bfloat16* __restrict__ EEp,
                              const int* __restrict__ off, const int* __restrict__ srcp,
                              const float* __restrict__ att, const float* __restrict__ bias,
                              const float* __restrict__ bng, const float* __restrict__ bnb,
                              const float* __restrict__ bnrm, const float* __restrict__ bnrv,
                              const float* __restrict__ residual,
                              float* __restrict__ outp, int bnrelu) {
    int gw   = (blockIdx.x * blockDim.x + threadIdx.x) >> 5;
    int lane = threadIdx.x & 31;
    if (gw >= n_nodes) return;
    const int n = gw;
    const int base = lane * 8;

    float xr[8], atv[8];
    {
        float4 t0 = *(const float4*)(XR + (size_t)n * C2 + base);
        float4 t1 = *(const float4*)(XR + (size_t)n * C2 + base + 4);
        xr[0]=t0.x; xr[1]=t0.y; xr[2]=t0.z; xr[3]=t0.w;
        xr[4]=t1.x; xr[5]=t1.y; xr[6]=t1.z; xr[7]=t1.w;
        float4 u0 = *(const float4*)(att + base);
        float4 u1 = *(const float4*)(att + base + 4);
        atv[0]=u0.x; atv[1]=u0.y; atv[2]=u0.z; atv[3]=u0.w;
        atv[4]=u1.x; atv[5]=u1.y; atv[6]=u1.z; atv[7]=u1.w;
    }

    float m = -1e30f, dsum = 0.f;
    float acc[8];
    #pragma unroll
    for (int j = 0; j < 8; j++) acc[j] = 0.f;

    const int i0 = off[n], i1 = off[n + 1];
    for (int idx = i0; idx < i1; ++idx) {
        int s = srcp[idx];
        float el[8];
        {
            float4 t0 = *(const float4*)(XL + (size_t)s * C2 + base);
            float4 t1 = *(const float4*)(XL + (size_t)s * C2 + base + 4);
            el[0]=t0.x; el[1]=t0.y; el[2]=t0.z; el[3]=t0.w;
            el[4]=t1.x; el[5]=t1.y; el[6]=t1.z; el[7]=t1.w;
        }
        float p = 0.f;
        {
            uint4 t = *(const uint4*)(EEp + (size_t)idx * C2 + base);
            uint32_t u[4] = {t.x, t.y, t.z, t.w};
            #pragma unroll
            for (int q = 0; q < 4; q++) {
                __nv_bfloat162 b2 = *(__nv_bfloat162*)&u[q];
                float2 f2 = __bfloat1622float2(b2);
                float z0 = el[2*q]   + xr[2*q]   + f2.x;
                float z1 = el[2*q+1] + xr[2*q+1] + f2.y;
                z0 = (z0 > 0.f) ? z0 : 0.2f * z0;
                z1 = (z1 > 0.f) ? z1 : 0.2f * z1;
                p = fmaf(z0, atv[2*q], p);
                p = fmaf(z1, atv[2*q+1], p);
            }
        }
        p += __shfl_xor_sync(0xffffffffu, p, 1);
        p += __shfl_xor_sync(0xffffffffu, p, 2);
        p += __shfl_xor_sync(0xffffffffu, p, 4);
        float nm = fmaxf(m, p);
        float sc = __expf(m - nm);
        float f  = __expf(p - nm);
        dsum = dsum * sc + f;
        #pragma unroll
        for (int j = 0; j < 8; j++) acc[j] = fmaf(acc[j], sc, f * el[j]);
        m = nm;
    }

    float inv = (i1 > i0) ? (1.0f / dsum) : 0.f;
    float v[8];
    #pragma unroll
    for (int j = 0; j < 8; j++) {
        float t = acc[j] * inv;
        t += __shfl_xor_sync(0xffffffffu, t, 8);
        t += __shfl_xor_sync(0xffffffffu, t, 16);
        v[j] = t * 0.25f;
    }

    if (lane < 8) {
        int c0 = lane * 8;
        #pragma unroll
        for (int j = 0; j < 8; j++) {
            int c = c0 + j;
            float t = v[j] + bias[c];
            if (bnrelu) {
                t = (t - bnrm[c]) * rsqrtf(bnrv[c] + 1e-5f) * bng[c] + bnb[c];
                t += residual[(size_t)n * HIDC + c];
                t = fmaxf(t, 0.f);
            }
            outp[(size_t)n * HIDC + c] = t;
        }
    }
}

__global__ void copy_f4(const float4* __restrict__ s, float4* __restrict__ d, int n4) {
    int i = blockIdx.x * blockDim.x + threadIdx.x;
    int stride = gridDim.x * blockDim.x;
    for (; i < n4; i += stride) d[i] = s[i];
}

static inline int cdiv(int a, int b) { return (a + b - 1) / b; }
static inline size_t img_bytes(int K, int N) { return (size_t)4 * K * N; }
static inline int smem_bytes(int K, int BN) {
    return 2 * (128 * (K + 8) * 2) + 2 * (K * (BN + 8) * 2);
}

extern "C" void kernel_launch(void* const* d_in, const int* in_sizes, int n_in,
                              void* d_out, int out_size) {
    const float* x      = (const float*)d_in[0];
    const int*   ei     = (const int*)  d_in[1];
    const float* ea     = (const float*)d_in[2];
    const float* res_W  = (const float*)d_in[3];
    const float* res_b  = (const float*)d_in[4];
    const float* Wl0    = (const float*)d_in[5];
    const float* bl0    = (const float*)d_in[6];
    const float* Wr0    = (const float*)d_in[7];
    const float* br0    = (const float*)d_in[8];
    const float* We0    = (const float*)d_in[9];
    const float* att0   = (const float*)d_in[10];
    const float* bias0  = (const float*)d_in[11];
    const float* Wl12   = (const float*)d_in[12];
    const float* bl12   = (const float*)d_in[13];
    const float* Wr12   = (const float*)d_in[14];
    const float* br12   = (const float*)d_in[15];
    const float* We12   = (const float*)d_in[16];
    const float* att12  = (const float*)d_in[17];
    const float* bias12 = (const float*)d_in[18];
    const float* bng    = (const float*)d_in[19];
    const float* bnb    = (const float*)d_in[20];
    const float* bnrm   = (const float*)d_in[21];
    const float* bnrv   = (const float*)d_in[22];

    const int N = in_sizes[0] / CIN;
    const int E = in_sizes[1] / 2;
    const int* srcpin = ei;
    const int* dstpin = ei + E;
    float* out = (float*)d_out;

    float *XL, *XR, *H0, *H1, *RES;
    __nv_bfloat16* EE;
    int *off, *cur, *pos, *srcp, *cnt, *bsum;
    char* Bimg;
    cudaGetSymbolAddress((void**)&XL,  g_XL);
    cudaGetSymbolAddress((void**)&XR,  g_XR);
    cudaGetSymbolAddress((void**)&EE,  g_EE);
    cudaGetSymbolAddress((void**)&H0,  g_H0);
    cudaGetSymbolAddress((void**)&H1,  g_H1);
    cudaGetSymbolAddress((void**)&RES, g_RES);
    cudaGetSymbolAddress((void**)&off, g_off);
    cudaGetSymbolAddress((void**)&cur, g_cur);
    cudaGetSymbolAddress((void**)&pos, g_pos);
    cudaGetSymbolAddress((void**)&srcp,g_srcp);
    cudaGetSymbolAddress((void**)&cnt, g_cnt);
    cudaGetSymbolAddress((void**)&bsum,g_bsum);
    cudaGetSymbolAddress((void**)&Bimg,g_Bimg);

    cudaFuncSetAttribute(tc_gemm,      cudaFuncAttributeMaxDynamicSharedMemorySize, smem_bytes(128, 128));
    cudaFuncSetAttribute(tc_gemm_edge, cudaFuncAttributeMaxDynamicSharedMemorySize, smem_bytes(128, 256));

    // ---- weight image offsets (4 bytes per element: hi+lo bf16) ----
    size_t o = 0;
    const size_t OFF_RES = o; o += img_bytes(128, 64);
    const size_t OFF_WL0 = o; o += img_bytes(128, 256);
    const size_t OFF_WR0 = o; o += img_bytes(128, 256);
    const size_t OFF_WE0 = o; o += img_bytes(128, 256);
    const size_t OFF_WL1 = o; o += img_bytes(64, 256);
    const size_t OFF_WR1 = o; o += img_bytes(64, 256);
    const size_t OFF_WE1 = o; o += img_bytes(128, 256);
    const size_t OFF_WL2 = o; o += img_bytes(64, 256);
    const size_t OFF_WR2 = o; o += img_bytes(64, 256);
    const size_t OFF_WE2 = o; o += img_bytes(128, 256);

    #define IMG(off) ((__nv_bfloat16*)(Bimg + (off)))
    prep_B<<<cdiv(128 *  64, 256), 256>>>(res_W,            128,  64, IMG(OFF_RES));
    prep_B<<<cdiv(128 * 256, 256), 256>>>(Wl0,              128, 256, IMG(OFF_WL0));
    prep_B<<<cdiv(128 * 256, 256), 256>>>(Wr0,              128, 256, IMG(OFF_WR0));
    prep_B<<<cdiv(128 * 256, 256), 256>>>(We0,              128, 256, IMG(OFF_WE0));
    prep_B<<<cdiv( 64 * 256, 256), 256>>>(Wl12,              64, 256, IMG(OFF_WL1));
    prep_B<<<cdiv( 64 * 256, 256), 256>>>(Wr12,              64, 256, IMG(OFF_WR1));
    prep_B<<<cdiv(128 * 256, 256), 256>>>(We12,             128, 256, IMG(OFF_WE1));
    prep_B<<<cdiv( 64 * 256, 256), 256>>>(Wl12 + HIDC * C2,  64, 256, IMG(OFF_WL2));
    prep_B<<<cdiv( 64 * 256, 256), 256>>>(Wr12 + HIDC * C2,  64, 256, IMG(OFF_WR2));
    prep_B<<<cdiv(128 * 256, 256), 256>>>(We12 + CIN * C2,  128, 256, IMG(OFF_WE2));

    // ---- CSR by destination (also permutes src, records per-edge slot) ----
    cudaMemsetAsync(cnt, 0, sizeof(int) * N);
    hist_kernel<<<cdiv(E, 256), 256>>>(dstpin, E, cnt);
    int nb = cdiv(N, 1024);
    scan_block<<<nb, 1024>>>(cnt, N, off, bsum);
    scan_small<<<1, 32>>>(bsum, nb);
    finalize_offsets<<<cdiv(N, 256), 256>>>(N, E, bsum, off, cur);
    scatter_kernel<<<cdiv(E, 256), 256>>>(dstpin, srcpin, E, cur, pos, srcp);

    const int smN128 = smem_bytes(128, 128);
    const int smN64  = smem_bytes(64, 128);
    const int smE128 = smem_bytes(128, 256);
    dim3 gN2(cdiv(N, 128), 2);
    int  gE1 = cdiv(E, 128);
    dim3 gR (cdiv(N, 128), 1);
    int aggGrid = cdiv(N * 32, 256);

    // ---- residual projection ----
    tc_gemm<<<gR, 256, smN128>>>(N, 128, 64, x, IMG(OFF_RES), res_b, RES);

    // ---- layer 0 ----
    tc_gemm<<<gN2, 256, smN128>>>(N, 128, 256, x,  IMG(OFF_WL0), bl0, XL);
    tc_gemm<<<gN2, 256, smN128>>>(N, 128, 256, x,  IMG(OFF_WR0), br0, XR);
    tc_gemm_edge<<<gE1, 256, smE128>>>(E, 128, ea, IMG(OFF_WE0), pos, EE);
    gat_aggregate<<<aggGrid, 256>>>(N, XL, XR, EE, off, srcp,
                                    att0, bias0, bng, bnb, bnrm, bnrv, RES, H0, 1);

    // ---- layer 1 ----
    tc_gemm<<<gN2, 256, smN64>>>(N, 64, 256, H0, IMG(OFF_WL1), bl12, XL);
    tc_gemm<<<gN2, 256, smN64>>>(N, 64, 256, H0, IMG(OFF_WR1), br12, XR);
    tc_gemm_edge<<<gE1, 256, smE128>>>(E, 128, ea, IMG(OFF_WE1), pos, EE);
    gat_aggregate<<<aggGrid, 256>>>(N, XL, XR, EE, off, srcp,
                                    att12, bias12, bng + HIDC, bnb + HIDC,
                                    bnrm + HIDC, bnrv + HIDC, H0, H1, 1);

    // ---- layer 2 (final conv) ----
    tc_gemm<<<gN2, 256, smN64>>>(N, 64, 256, H1, IMG(OFF_WL2), bl12 + C2, XL);
    tc_gemm<<<gN2, 256, smN64>>>(N, 64, 256, H1, IMG(OFF_WR2), br12 + C2, XR);
    tc_gemm_edge<<<gE1, 256, smE128>>>(E, 128, ea, IMG(OFF_WE2), pos, EE);
    gat_aggregate<<<aggGrid, 256>>>(N, XL, XR, EE, off, srcp,
                                    att12 + C2, bias12 + HIDC,
                                    nullptr, nullptr, nullptr, nullptr, nullptr, out, 0);

    // ---- second output: edge_attr passthrough ----
    copy_f4<<<4096, 256>>>((const float4*)ea, (float4*)(out + (size_t)N * HIDC),
                           E * CIN / 4);
    #undef IMG
}

// round 11
// speedup vs baseline: 1.8054x; 1.1689x over previous
#include <cuda_runtime.h>
#include <cuda_bf16.h>
#include <math.h>
#include <stdint.h>

// Problem constants (match reference setup_inputs)
#define NN    50000
#define EEDG  500000
#define CIN   128
#define HIDC  64
#define NHEAD 4
#define C2    256   // NHEAD * HIDC

// =================== scratch (static __device__) ===================
__device__ float g_XL [NN * C2];
__device__ float g_XR [NN * C2];
__device__ __nv_bfloat16 g_EE0[(size_t)EEDG * C2];   // 256 MB each, CSR-permuted rows
__device__ __nv_bfloat16 g_EE1[(size_t)EEDG * C2];
__device__ __nv_bfloat16 g_EE2[(size_t)EEDG * C2];
__device__ float g_H0 [NN * HIDC];
__device__ float g_H1 [NN * HIDC];
__device__ float g_RES[NN * HIDC];
__device__ int   g_off[NN + 1];
__device__ int   g_cur[NN];
__device__ int   g_pos[EEDG];      // CSR slot of edge e
__device__ int   g_srcp[EEDG];     // src node, permuted to CSR order
__device__ int   g_cnt[NN];
__device__ int   g_bsum[64];
__device__ __align__(16) char g_Bimg[950272];   // bf16 hi/lo weight images (plain row-major)

// =================== PTX helpers (compute_103-legal only) ===================
__device__ __forceinline__ uint32_t smem_to_u32(const void* p) {
    uint32_t a;
    asm("{ .reg .u64 t; cvta.to.shared.u64 t, %1; cvt.u32.u64 %0, t; }" : "=r"(a) : "l"(p));
    return a;
}
__device__ __forceinline__ void ldsm4(uint32_t* r, uint32_t a) {
    asm volatile("ldmatrix.sync.aligned.m8n8.x4.shared.b16 {%0,%1,%2,%3}, [%4];"
        : "=r"(r[0]), "=r"(r[1]), "=r"(r[2]), "=r"(r[3]) : "r"(a));
}
__device__ __forceinline__ void ldsm4t(uint32_t* r, uint32_t a) {
    asm volatile("ldmatrix.sync.aligned.m8n8.x4.trans.shared.b16 {%0,%1,%2,%3}, [%4];"
        : "=r"(r[0]), "=r"(r[1]), "=r"(r[2]), "=r"(r[3]) : "r"(a));
}
__device__ __forceinline__ void mma16816(float* c, const uint32_t* a, const uint32_t* b) {
    asm volatile(
        "mma.sync.aligned.m16n8k16.row.col.f32.bf16.bf16.f32 "
        "{%0,%1,%2,%3}, {%4,%5,%6,%7}, {%8,%9}, {%0,%1,%2,%3};"
        : "+f"(c[0]), "+f"(c[1]), "+f"(c[2]), "+f"(c[3])
        : "r"(a[0]), "r"(a[1]), "r"(a[2]), "r"(a[3]), "r"(b[0]), "r"(b[1]));
}

// =================== CSR build ===================
__global__ void hist_kernel(const int* __restrict__ dst, int E, int* __restrict__ cnt) {
    int e = blockIdx.x * blockDim.x + threadIdx.x;
    if (e < E) atomicAdd(&cnt[dst[e]], 1);
}
__global__ void scan_block(const int* __restrict__ cnt, int N,
                           int* __restrict__ off, int* __restrict__ bsum) {
    __shared__ int s[1024];
    int i = blockIdx.x * 1024 + threadIdx.x;
    int v = (i < N) ? cnt[i] : 0;
    s[threadIdx.x] = v;
    __syncthreads();
    #pragma unroll
    for (int d = 1; d < 1024; d <<= 1) {
        int t = (threadIdx.x >= d) ? s[threadIdx.x - d] : 0;
        __syncthreads();
        if (threadIdx.x >= d) s[threadIdx.x] += t;
        __syncthreads();
    }
    if (i < N) off[i] = s[threadIdx.x] - v;
    if (threadIdx.x == 1023) bsum[blockIdx.x] = s[1023];
}
// finalize with integrated bsum prefix (bsum has <=49 entries; cached loop)
__global__ void finalize2(int N, int E, const int* __restrict__ bsum,
                          int* __restrict__ off, int* __restrict__ cur) {
    int i = blockIdx.x * blockDim.x + threadIdx.x;
    if (i < N) {
        int b = i >> 10, s = 0;
        for (int q = 0; q < b; q++) s += bsum[q];
        int v = off[i] + s;
        off[i] = v;
        cur[i] = v;
    }
    if (i == 0) off[N] = E;
}
__global__ void scatter_kernel(const int* __restrict__ dst, const int* __restrict__ src,
                               int E, int* __restrict__ cur,
                               int* __restrict__ pos, int* __restrict__ srcp) {
    int e = blockIdx.x * blockDim.x + threadIdx.x;
    if (e < E) {
        int p = atomicAdd(&cur[dst[e]], 1);
        pos[e] = p;
        srcp[p] = src[e];
    }
}

// =================== single prep kernel: all 10 weights -> bf16 hi/lo images ===================
__device__ __forceinline__ void prep_one(const float* __restrict__ W, int j, int KN,
                                         __nv_bfloat16* __restrict__ img) {
    float a = W[j];
    __nv_bfloat16 h = __float2bfloat16(a);
    __nv_bfloat16 l = __float2bfloat16(a - __bfloat162float(h));
    img[j] = h;
    img[KN + j] = l;
}
// image offsets (bytes): each weight takes 4*K*N bytes (hi then lo, 2B each)
#define OFF_RES 0
#define OFF_WL0 (OFF_RES + 4 * 128 * 64)
#define OFF_WR0 (OFF_WL0 + 4 * 128 * 256)
#define OFF_WE0 (OFF_WR0 + 4 * 128 * 256)
#define OFF_WL1 (OFF_WE0 + 4 * 128 * 256)
#define OFF_WR1 (OFF_WL1 + 4 * 64 * 256)
#define OFF_WE1 (OFF_WR1 + 4 * 64 * 256)
#define OFF_WL2 (OFF_WE1 + 4 * 128 * 256)
#define OFF_WR2 (OFF_WL2 + 4 * 64 * 256)
#define OFF_WE2 (OFF_WR2 + 4 * 64 * 256)

__global__ void prep_all(const float* __restrict__ resW,
                         const float* __restrict__ Wl0, const float* __restrict__ Wr0,
                         const float* __restrict__ We0,
                         const float* __restrict__ Wl12, const float* __restrict__ Wr12,
                         const float* __restrict__ We12,
                         char* __restrict__ img) {
    int i = blockIdx.x * blockDim.x + threadIdx.x;
    const int S0 = 128 * 64;        // RES
    const int S1 = 128 * 256;       // WL0/WR0/WE0/WE1/WE2
    const int S2 = 64 * 256;        // WL1/WR1/WL2/WR2
    int t = i;
    if (t < S0) { prep_one(resW, t, S0, (__nv_bfloat16*)(img + OFF_RES)); return; } t -= S0;
    if (t < S1) { prep_one(Wl0,  t, S1, (__nv_bfloat16*)(img + OFF_WL0)); return; } t -= S1;
    if (t < S1) { prep_one(Wr0,  t, S1, (__nv_bfloat16*)(img + OFF_WR0)); return; } t -= S1;
    if (t < S1) { prep_one(We0,  t, S1, (__nv_bfloat16*)(img + OFF_WE0)); return; } t -= S1;
    if (t < S2) { prep_one(Wl12, t, S2, (__nv_bfloat16*)(img + OFF_WL1)); return; } t -= S2;
    if (t < S2) { prep_one(Wr12, t, S2, (__nv_bfloat16*)(img + OFF_WR1)); return; } t -= S2;
    if (t < S1) { prep_one(We12, t, S1, (__nv_bfloat16*)(img + OFF_WE1)); return; } t -= S1;
    if (t < S2) { prep_one(Wl12 + S2, t, S2, (__nv_bfloat16*)(img + OFF_WL2)); return; } t -= S2;
    if (t < S2) { prep_one(Wr12 + S2, t, S2, (__nv_bfloat16*)(img + OFF_WR2)); return; } t -= S2;
    if (t < S1) { prep_one(We12 + S1, t, S1, (__nv_bfloat16*)(img + OFF_WE2)); return; }
}
#define PREP_TOTAL (128*64 + 4*(128*256) + 4*(64*256) + 128*256)

// =================== GEMM building blocks ===================
// A tile: fp32 -> bf16 hi/lo into smem (padded rows K+8); optional passthrough store.
template<int K>
__device__ __forceinline__ void fill_A(int M, int m0, const float* __restrict__ A,
                                       char* smem, float* __restrict__ pass) {
    const int PA = K + 8;
    const uint32_t A_sz = (uint32_t)128 * PA * 2;
    char* Ah = smem;
    char* Al = smem + A_sz;
    const int rf4 = K >> 2;
    for (int idx = threadIdx.x; idx < 128 * rf4; idx += 256) {
        int row = idx / rf4, col = (idx - row * rf4) * 4;
        int gr = m0 + row;
        float4 v = make_float4(0.f, 0.f, 0.f, 0.f);
        if (gr < M) {
            v = *(const float4*)(A + (size_t)gr * K + col);
            if (pass) *(float4*)(pass + (size_t)gr * K + col) = v;
        }
        float f[4] = {v.x, v.y, v.z, v.w};
        uint32_t hp[2], lp[2];
        #pragma unroll
        for (int q = 0; q < 2; q++) {
            float a0 = f[2 * q], a1 = f[2 * q + 1];
            __nv_bfloat16 h0 = __float2bfloat16(a0), h1 = __float2bfloat16(a1);
            __nv_bfloat16 l0 = __float2bfloat16(a0 - __bfloat162float(h0));
            __nv_bfloat16 l1 = __float2bfloat16(a1 - __bfloat162float(h1));
            hp[q] = ((uint32_t)__bfloat16_as_ushort(h1) << 16) | __bfloat16_as_ushort(h0);
            lp[q] = ((uint32_t)__bfloat16_as_ushort(l1) << 16) | __bfloat16_as_ushort(l0);
        }
        uint32_t boff = ((uint32_t)row * PA + col) * 2;
        *(uint32_t*)(Ah + boff)     = hp[0];
        *(uint32_t*)(Ah + boff + 4) = hp[1];
        *(uint32_t*)(Al + boff)     = lp[0];
        *(uint32_t*)(Al + boff + 4) = lp[1];
    }
}
// B tile (full 256 cols, padded 264): copy hi/lo images from global.
template<int K>
__device__ __forceinline__ void fill_B(const __nv_bfloat16* __restrict__ Bimg, char* Bh) {
    char* Bl = Bh + (uint32_t)K * 264 * 2;
    const __nv_bfloat16* gh = Bimg;
    const __nv_bfloat16* gl = Bimg + K * 256;
    for (int idx = threadIdx.x; idx < K * 32; idx += 256) {
        int row = idx >> 5, col = (idx & 31) * 8;
        uint4 vh = *(const uint4*)(gh + row * 256 + col);
        uint4 vl = *(const uint4*)(gl + row * 256 + col);
        uint32_t boff = ((uint32_t)row * 264 + col) * 2;
        *(uint4*)(Bh + boff) = vh;
        *(uint4*)(Bl + boff) = vl;
    }
}
// NT=8 mainloop: hi*hi + hi*lo + lo*hi, warp tile 64x64, CTA 128x256.
template<int K>
__device__ __forceinline__ void mainloop8(char* smem, float R[4][8][4]) {
    const int PA = K + 8, PB = 264;
    const uint32_t A_sz = (uint32_t)128 * PA * 2;
    const uint32_t B_sz = (uint32_t)K * PB * 2;
    const int wid = threadIdx.x >> 5, lane = threadIdx.x & 31;
    const int wm = (wid >> 2) * 64;
    const int wn = (wid & 3) * 64;
    const int lr = lane & 15, lc = lane >> 4;

    #pragma unroll
    for (int i = 0; i < 4; i++)
        #pragma unroll
        for (int j = 0; j < 8; j++)
            #pragma unroll
            for (int q = 0; q < 4; q++) R[i][j][q] = 0.f;

    const uint32_t su = smem_to_u32(smem);
    const uint32_t aAddr0 = su + (((uint32_t)(wm + lr) * PA + lc * 8) * 2);
    const uint32_t bAddr0 = su + 2 * A_sz + (((uint32_t)lr * PB + wn + lc * 8) * 2);
    const int ksteps = K >> 4;

    for (int ks = 0; ks < ksteps; ks++) {
        const uint32_t ka = aAddr0 + (uint32_t)ks * 32;
        const uint32_t kb = bAddr0 + (uint32_t)ks * 16 * PB * 2;
        uint32_t a[4][4], bh[8][2], bl[8][2];
        #pragma unroll
        for (int mi = 0; mi < 4; mi++) ldsm4(a[mi], ka + (uint32_t)mi * 16 * PA * 2);
        #pragma unroll
        for (int nj = 0; nj < 4; nj++) {
            uint32_t t[4];
            ldsm4t(t, kb + (uint32_t)nj * 32);
            bh[2 * nj][0] = t[0]; bh[2 * nj][1] = t[1];
            bh[2 * nj + 1][0] = t[2]; bh[2 * nj + 1][1] = t[3];
            ldsm4t(t, kb + B_sz + (uint32_t)nj * 32);
            bl[2 * nj][0] = t[0]; bl[2 * nj][1] = t[1];
            bl[2 * nj + 1][0] = t[2]; bl[2 * nj + 1][1] = t[3];
        }
        #pragma unroll
        for (int mi = 0; mi < 4; mi++)
            #pragma unroll
            for (int ni = 0; ni < 8; ni++) mma16816(R[mi][ni], a[mi], bh[ni]);
        #pragma unroll
        for (int mi = 0; mi < 4; mi++)
            #pragma unroll
            for (int ni = 0; ni < 8; ni++) mma16816(R[mi][ni], a[mi], bl[ni]);
        #pragma unroll
        for (int mi = 0; mi < 4; mi++) ldsm4(a[mi], ka + A_sz + (uint32_t)mi * 16 * PA * 2);
        #pragma unroll
        for (int mi = 0; mi < 4; mi++)
            #pragma unroll
            for (int ni = 0; ni < 8; ni++) mma16816(R[mi][ni], a[mi], bh[ni]);
    }
}

// ---- merged edge GEMM: A filled once, 3 weight sets, bf16 EE at CSR slots + passthrough ----
__global__ __launch_bounds__(256) void tc_gemm_edge3(
    int E, const float* __restrict__ A,
    const __nv_bfloat16* __restrict__ B0, const __nv_bfloat16* __restrict__ B1,
    const __nv_bfloat16* __restrict__ B2,
    const int* __restrict__ pos,
    __nv_bfloat16* __restrict__ E0, __nv_bfloat16* __restrict__ E1,
    __nv_bfloat16* __restrict__ E2,
    float* __restrict__ pass)
{
    extern __shared__ char smem[];
    constexpr int K = 128;
    const uint32_t A_sz = (uint32_t)128 * (K + 8) * 2;
    const int m0 = blockIdx.x * 128;
    const int wid = threadIdx.x >> 5, lane = threadIdx.x & 31;
    const int wm = (wid >> 2) * 64, wn = (wid & 3) * 64;

    fill_A<K>(E, m0, A, smem, pass);

    const __nv_bfloat16* Bs[3] = {B0, B1, B2};
    __nv_bfloat16* Es[3] = {E0, E1, E2};

    #pragma unroll 1
    for (int s = 0; s < 3; s++) {
        __syncthreads();                     // A done (s=0) / prev mainloop done reading B
        fill_B<K>(Bs[s], smem + 2 * A_sz);
        __syncthreads();
        float R[4][8][4];
        mainloop8<K>(smem, R);
        __nv_bfloat16* EEs = Es[s];
        #pragma unroll
        for (int mi = 0; mi < 4; mi++) {
            #pragma unroll
            for (int half = 0; half < 2; half++) {
                int row = m0 + wm + mi * 16 + (lane >> 2) + half * 8;
                if (row < E) {
                    int p = pos[row];
                    uint32_t* dp = (uint32_t*)(EEs + (size_t)p * C2 + wn + (lane & 3) * 2);
                    #pragma unroll
                    for (int ni = 0; ni < 8; ni++) {
                        __nv_bfloat16 h0 = __float2bfloat16(R[mi][ni][half * 2 + 0]);
                        __nv_bfloat16 h1 = __float2bfloat16(R[mi][ni][half * 2 + 1]);
                        dp[ni * 4] = ((uint32_t)__bfloat16_as_ushort(h1) << 16)
                                   | __bfloat16_as_ushort(h0);
                    }
                }
            }
        }
    }
}

// ---- merged node GEMM: shared A, 2 weight sets (WL, WR), fp32 out + bias ----
template<int K>
__global__ __launch_bounds__(256) void tc_gemm_node2(
    int M, const float* __restrict__ A,
    const __nv_bfloat16* __restrict__ B0, const __nv_bfloat16* __restrict__ B1,
    const float* __restrict__ bias0, const float* __restrict__ bias1,
    float* __restrict__ C0, float* __restrict__ C1)
{
    extern __shared__ char smem[];
    const uint32_t A_sz = (uint32_t)128 * (K + 8) * 2;
    const int m0 = blockIdx.x * 128;
    const int wid = threadIdx.x >> 5, lane = threadIdx.x & 31;
    const int wm = (wid >> 2) * 64, wn = (wid & 3) * 64;

    fill_A<K>(M, m0, A, smem, nullptr);

    const __nv_bfloat16* Bs[2] = {B0, B1};
    const float* bs[2] = {bias0, bias1};
    float* Cs[2] = {C0, C1};

    #pragma unroll 1
    for (int s = 0; s < 2; s++) {
        __syncthreads();
        fill_B<K>(Bs[s], smem + 2 * A_sz);
        __syncthreads();
        float R[4][8][4];
        mainloop8<K>(smem, R);
        const float* bb = bs[s];
        float* CC = Cs[s];
        #pragma unroll
        for (int mi = 0; mi < 4; mi++) {
            int row = m0 + wm + mi * 16 + (lane >> 2);
            #pragma unroll
            for (int ni = 0; ni < 8; ni++) {
                int col = wn + ni * 8 + (lane & 3) * 2;
                float b0 = bb[col], b1 = bb[col + 1];
                if (row < M) {
                    float2 v = make_float2(R[mi][ni][0] + b0, R[mi][ni][1] + b1);
                    *(float2*)(CC + (size_t)row * C2 + col) = v;
                }
                if (row + 8 < M) {
                    float2 v = make_float2(R[mi][ni][2] + b0, R[mi][ni][3] + b1);
                    *(float2*)(CC + (size_t)(row + 8) * C2 + col) = v;
                }
            }
        }
    }
}

// ---- residual projection GEMM (NT=4 core, N=64) ----
template<int NT>
__device__ __forceinline__ void gemm_core(
    int M, int K, const float* __restrict__ A, const __nv_bfloat16* __restrict__ Bimg,
    int Nfull, int m0, int n0, char* smem, float R[4][NT][4])
{
    const int BN = NT * 32;
    const int tid = threadIdx.x, wid = tid >> 5, lane = tid & 31;
    const int PA = K + 8, PB = BN + 8;
    const uint32_t A_sz = (uint32_t)128 * PA * 2;
    const uint32_t B_sz = (uint32_t)K * PB * 2;
    char* Bh = smem + 2 * A_sz;
    char* Bl = smem + 2 * A_sz + B_sz;

    fill_A<128>(M, m0, A, smem, nullptr);   // residual always K=128
    {
        const __nv_bfloat16* gh = Bimg;
        const __nv_bfloat16* gl = Bimg + (size_t)K * Nfull;
        const int c8 = BN / 8;
        for (int idx = tid; idx < K * c8; idx += 256) {
            int row = idx / c8, col = (idx - row * c8) * 8;
            uint4 vh = make_uint4(0, 0, 0, 0), vl = vh;
            if (n0 + col < Nfull) {
                vh = *(const uint4*)(gh + (size_t)row * Nfull + n0 + col);
                vl = *(const uint4*)(gl + (size_t)row * Nfull + n0 + col);
            }
            uint32_t boff = ((uint32_t)row * PB + col) * 2;
            *(uint4*)(Bh + boff) = vh;
            *(uint4*)(Bl + boff) = vl;
        }
    }
    __syncthreads();

    const int wm = (wid >> 2) * 64;
    const int wn = (wid & 3) * (NT * 8);
    const int lr = lane & 15, lc = lane >> 4;

    #pragma unroll
    for (int i = 0; i < 4; i++)
        #pragma unroll
        for (int j = 0; j < NT; j++)
            #pragma unroll
            for (int q = 0; q < 4; q++) R[i][j][q] = 0.f;

    const uint32_t su = smem_to_u32(smem);
    const uint32_t aAddr0 = su + (((uint32_t)(wm + lr) * PA + lc * 8) * 2);
    const uint32_t bAddr0 = su + 2 * A_sz + (((uint32_t)lr * PB + wn + lc * 8) * 2);
    const int ksteps = K >> 4;

    for (int ks = 0; ks < ksteps; ks++) {
        const uint32_t ka = aAddr0 + (uint32_t)ks * 32;
        const uint32_t kb = bAddr0 + (uint32_t)ks * 16 * PB * 2;
        uint32_t a[4][4], bh[NT][2], bl[NT][2];
        #pragma unroll
        for (int mi = 0; mi < 4; mi++) ldsm4(a[mi], ka + (uint32_t)mi * 16 * PA * 2);
        #pragma unroll
        for (int nj = 0; nj < NT / 2; nj++) {
            uint32_t t[4];
            ldsm4t(t, kb + (uint32_t)nj * 32);
            bh[2 * nj][0] = t[0]; bh[2 * nj][1] = t[1];
            bh[2 * nj + 1][0] = t[2]; bh[2 * nj + 1][1] = t[3];
            ldsm4t(t, kb + B_sz + (uint32_t)nj * 32);
            bl[2 * nj][0] = t[0]; bl[2 * nj][1] = t[1];
            bl[2 * nj + 1][0] = t[2]; bl[2 * nj + 1][1] = t[3];
        }
        #pragma unroll
        for (int mi = 0; mi < 4; mi++)
            #pragma unroll
            for (int ni = 0; ni < NT; ni++) mma16816(R[mi][ni], a[mi], bh[ni]);
        #pragma unroll
        for (int mi = 0; mi < 4; mi++)
            #pragma unroll
            for (int ni = 0; ni < NT; ni++) mma16816(R[mi][ni], a[mi], bl[ni]);
        #pragma unroll
        for (int mi = 0; mi < 4; mi++) ldsm4(a[mi], ka + A_sz + (uint32_t)mi * 16 * PA * 2);
        #pragma unroll
        for (int mi = 0; mi < 4; mi++)
            #pragma unroll
            for (int ni = 0; ni < NT; ni++) mma16816(R[mi][ni], a[mi], bh[ni]);
    }
}

__global__ __launch_bounds__(256) void tc_gemm_res(
    int M, const float* __restrict__ A, const __nv_bfloat16* __restrict__ Bimg,
    const float* __restrict__ bias, float* __restrict__ C)
{
    extern __shared__ char smem[];
    const int lane = threadIdx.x & 31, wid = threadIdx.x >> 5;
    const int m0 = blockIdx.x * 128;
    float R[4][4][4];
    gemm_core<4>(M, 128, A, Bimg, 64, m0, 0, smem, R);

    const int wm = (wid >> 2) * 64, wn = (wid & 3) * 32;
    #pragma unroll
    for (int mi = 0; mi < 4; mi++) {
        int row = m0 + wm + mi * 16 + (lane >> 2);
        #pragma unroll
        for (int ni = 0; ni < 4; ni++) {
            int col = wn + ni * 8 + (lane & 3) * 2;
            if (col < 64) {
                float b0 = bias[col], b1 = bias[col + 1];
                if (row < M) {
                    float2 v = make_float2(R[mi][ni][0] + b0, R[mi][ni][1] + b1);
                    *(float2*)(C + (size_t)row * 64 + col) = v;
                }
                if (row + 8 < M) {
                    float2 v = make_float2(R[mi][ni][2] + b0, R[mi][ni][3] + b1);
                    *(float2*)(C + (size_t)(row + 8) * 64 + col) = v;
                }
            }
        }
    }
}

// =================== fused GATv2 aggregation (one warp per destination node) ===================
__global__ void gat_aggregate(int n_nodes,
                              const float* __restrict__ XL, const float* __restrict__ XR,
                              const __nv_bfloat16* __restrict__ EEp,
                              const int* __restrict__ off, const int* __restrict__ srcp,
                              const float* __restrict__ att, const float* __restrict__ bias,
                              const float* __restrict__ bng, const float* __restrict__ bnb,
                              const float* __restrict__ bnrm, const float* __restrict__ bnrv,
                              const float* __restrict__ residual,
                              float* __restrict__ outp, int bnrelu) {
    int gw   = (blockIdx.x * blockDim.x + threadIdx.x) >> 5;
    int lane = threadIdx.x & 31;
    if (gw >= n_nodes) return;
    const int n = gw;
    const int base = lane * 8;

    float xr[8], atv[8];
    {
        float4 t0 = *(const float4*)(XR + (size_t)n * C2 + base);
        float4 t1 = *(const float4*)(XR + (size_t)n * C2 + base + 4);
        xr[0]=t0.x; xr[1]=t0.y; xr[2]=t0.z; xr[3]=t0.w;
        xr[4]=t1.x; xr[5]=t1.y; xr[6]=t1.z; xr[7]=t1.w;
        float4 u0 = *(const float4*)(att + base);
        float4 u1 = *(const float4*)(att + base + 4);
        atv[0]=u0.x; atv[1]=u0.y; atv[2]=u0.z; atv[3]=u0.w;
        atv[4]=u1.x; atv[5]=u1.y; atv[6]=u1.z; atv[7]=u1.w;
    }

    float m = -1e30f, dsum = 0.f;
    float acc[8];
    #pragma unroll
    for (int j = 0; j < 8; j++) acc[j] = 0.f;

    const int i0 = off[n], i1 = off[n + 1];
    for (int idx = i0; idx < i1; ++idx) {
        int s = srcp[idx];
        float el[8];
        {
            float4 t0 = *(const float4*)(XL + (size_t)s * C2 + base);
            float4 t1 = *(const float4*)(XL + (size_t)s * C2 + base + 4);
            el[0]=t0.x; el[1]=t0.y; el[2]=t0.z; el[3]=t0.w;
            el[4]=t1.x; el[5]=t1.y; el[6]=t1.z; el[7]=t1.w;
        }
        float p = 0.f;
        {
            uint4 t = *(const uint4*)(EEp + (size_t)idx * C2 + base);
            uint32_t u[4] = {t.x, t.y, t.z, t.w};
            #pragma unroll
            for (int q = 0; q < 4; q++) {
                __nv_bfloat162 b2 = *(__nv_bfloat162*)&u[q];
                float2 f2 = __bfloat1622float2(b2);
                float z0 = el[2*q]   + xr[2*q]   + f2.x;
                float z1 = el[2*q+1] + xr[2*q+1] + f2.y;
                z0 = (z0 > 0.f) ? z0 : 0.2f * z0;
                z1 = (z1 > 0.f) ? z1 : 0.2f * z1;
                p = fmaf(z0, atv[2*q], p);
                p = fmaf(z1, atv[2*q+1], p);
            }
        }
        p += __shfl_xor_sync(0xffffffffu, p, 1);
        p += __shfl_xor_sync(0xffffffffu, p, 2);
        p += __shfl_xor_sync(0xffffffffu, p, 4);
        float nm = fmaxf(m, p);
        float sc = __expf(m - nm);
        float f  = __expf(p - nm);
        dsum = dsum * sc + f;
        #pragma unroll
        for (int j = 0; j < 8; j++) acc[j] = fmaf(acc[j], sc, f * el[j]);
        m = nm;
    }

    float inv = (i1 > i0) ? (1.0f / dsum) : 0.f;
    float v[8];
    #pragma unroll
    for (int j = 0; j < 8; j++) {
        float t = acc[j] * inv;
        t += __shfl_xor_sync(0xffffffffu, t, 8);
        t += __shfl_xor_sync(0xffffffffu, t, 16);
        v[j] = t * 0.25f;
    }

    if (lane < 8) {
        int c0 = lane * 8;
        #pragma unroll
        for (int j = 0; j < 8; j++) {
            int c = c0 + j;
            float t = v[j] + bias[c];
            if (bnrelu) {
                t = (t - bnrm[c]) * rsqrtf(bnrv[c] + 1e-5f) * bng[c] + bnb[c];
                t += residual[(size_t)n * HIDC + c];
                t = fmaxf(t, 0.f);
            }
            outp[(size_t)n * HIDC + c] = t;
        }
    }
}

static inline int cdiv(int a, int b) { return (a + b - 1) / b; }
static inline int smem_nt8(int K) {    // NT=8 kernels (node2/edge3)
    return 2 * (128 * (K + 8) * 2) + 2 * (K * 264 * 2);
}
static inline int smem_res() {         // NT=4, K=128, BN=128
    return 2 * (128 * 136 * 2) + 2 * (128 * 136 * 2);
}

extern "C" void kernel_launch(void* const* d_in, const int* in_sizes, int n_in,
                              void* d_out, int out_size) {
    const float* x      = (const float*)d_in[0];
    const int*   ei     = (const int*)  d_in[1];
    const float* ea     = (const float*)d_in[2];
    const float* res_W  = (const float*)d_in[3];
    const float* res_b  = (const float*)d_in[4];
    const float* Wl0    = (const float*)d_in[5];
    const float* bl0    = (const float*)d_in[6];
    const float* Wr0    = (const float*)d_in[7];
    const float* br0    = (const float*)d_in[8];
    const float* We0    = (const float*)d_in[9];
    const float* att0   = (const float*)d_in[10];
    const float* bias0  = (const float*)d_in[11];
    const float* Wl12   = (const float*)d_in[12];
    const float* bl12   = (const float*)d_in[13];
    const float* Wr12   = (const float*)d_in[14];
    const float* br12   = (const float*)d_in[15];
    const float* We12   = (const float*)d_in[16];
    const float* att12  = (const float*)d_in[17];
    const float* bias12 = (const float*)d_in[18];
    const float* bng    = (const float*)d_in[19];
    const float* bnb    = (const float*)d_in[20];
    const float* bnrm   = (const float*)d_in[21];
    const float* bnrv   = (const float*)d_in[22];

    const int N = in_sizes[0] / CIN;
    const int E = in_sizes[1] / 2;
    const int* srcpin = ei;
    const int* dstpin = ei + E;
    float* out = (float*)d_out;

    float *XL, *XR, *H0, *H1, *RES;
    __nv_bfloat16 *EE0, *EE1, *EE2;
    int *off, *cur, *pos, *srcp, *cnt, *bsum;
    char* Bimg;
    cudaGetSymbolAddress((void**)&XL,  g_XL);
    cudaGetSymbolAddress((void**)&XR,  g_XR);
    cudaGetSymbolAddress((void**)&EE0, g_EE0);
    cudaGetSymbolAddress((void**)&EE1, g_EE1);
    cudaGetSymbolAddress((void**)&EE2, g_EE2);
    cudaGetSymbolAddress((void**)&H0,  g_H0);
    cudaGetSymbolAddress((void**)&H1,  g_H1);
    cudaGetSymbolAddress((void**)&RES, g_RES);
    cudaGetSymbolAddress((void**)&off, g_off);
    cudaGetSymbolAddress((void**)&cur, g_cur);
    cudaGetSymbolAddress((void**)&pos, g_pos);
    cudaGetSymbolAddress((void**)&srcp,g_srcp);
    cudaGetSymbolAddress((void**)&cnt, g_cnt);
    cudaGetSymbolAddress((void**)&bsum,g_bsum);
    cudaGetSymbolAddress((void**)&Bimg,g_Bimg);

    cudaFuncSetAttribute(tc_gemm_edge3,     cudaFuncAttributeMaxDynamicSharedMemorySize, smem_nt8(128));
    cudaFuncSetAttribute(tc_gemm_node2<128>,cudaFuncAttributeMaxDynamicSharedMemorySize, smem_nt8(128));
    cudaFuncSetAttribute(tc_gemm_node2<64>, cudaFuncAttributeMaxDynamicSharedMemorySize, smem_nt8(64));
    cudaFuncSetAttribute(tc_gemm_res,       cudaFuncAttributeMaxDynamicSharedMemorySize, smem_res());

    #define IMG(off_) ((const __nv_bfloat16*)(Bimg + (off_)))

    // ---- CSR by destination (4 kernel launches) ----
    cudaMemsetAsync(cnt, 0, sizeof(int) * N);
    hist_kernel<<<cdiv(E, 256), 256>>>(dstpin, E, cnt);                         // launch 1
    int nb = cdiv(N, 1024);
    scan_block<<<nb, 1024>>>(cnt, N, off, bsum);                                // 2
    finalize2<<<cdiv(N, 256), 256>>>(N, E, bsum, off, cur);                     // 3
    scatter_kernel<<<cdiv(E, 256), 256>>>(dstpin, srcpin, E, cur, pos, srcp);   // 4

    // ---- weight prep (1 launch) ----
    prep_all<<<cdiv(PREP_TOTAL, 256), 256>>>(res_W, Wl0, Wr0, We0,
                                             Wl12, Wr12, We12, Bimg);           // 5

    // ---- merged edge GEMM: all 3 layers' EE + passthrough (launch 6 — ncu target) ----
    tc_gemm_edge3<<<cdiv(E, 128), 256, smem_nt8(128)>>>(
        E, ea, IMG(OFF_WE0), IMG(OFF_WE1), IMG(OFF_WE2),
        pos, EE0, EE1, EE2, out + (size_t)N * HIDC);                            // 6

    const int gN = cdiv(N, 128);
    int aggGrid = cdiv(N * 32, 256);

    // ---- residual projection ----
    tc_gemm_res<<<gN, 256, smem_res()>>>(N, x, IMG(OFF_RES), res_b, RES);

    // ---- layer 0 ----
    tc_gemm_node2<128><<<gN, 256, smem_nt8(128)>>>(N, x, IMG(OFF_WL0), IMG(OFF_WR0),
                                                   bl0, br0, XL, XR);
    gat_aggregate<<<aggGrid, 256>>>(N, XL, XR, EE0, off, srcp,
                                    att0, bias0, bng, bnb, bnrm, bnrv, RES, H0, 1);

    // ---- layer 1 ----
    tc_gemm_node2<64><<<gN, 256, smem_nt8(64)>>>(N, H0, IMG(OFF_WL1), IMG(OFF_WR1),
                                                 bl12, br12, XL, XR);
    gat_aggregate<<<aggGrid, 256>>>(N, XL, XR, EE1, off, srcp,
                                    att12, bias12, bng + HIDC, bnb + HIDC,
                                    bnrm + HIDC, bnrv + HIDC, H0, H1, 1);

    // ---- layer 2 (final conv) ----
    tc_gemm_node2<64><<<gN, 256, smem_nt8(64)>>>(N, H1, IMG(OFF_WL2), IMG(OFF_WR2),
                                                 bl12 + C2, br12 + C2, XL, XR);
    gat_aggregate<<<aggGrid, 256>>>(N, XL, XR, EE2, off, srcp,
                                    att12 + C2, bias12 + HIDC,
                                    nullptr, nullptr, nullptr, nullptr, nullptr, out, 0);

    #undef IMG
}